// round 2
// baseline (speedup 1.0000x reference)
#include <cuda_runtime.h>
#include <cstddef>

#define BATCH 32
#define NPTS1 8192
#define M1 512
#define KNN1 32
#define M2 128
#define KNN2 64
// SA2 operates on the 512 SA1 centroids
#define NPTS2 512

// ---------------- scratch (static device globals; no allocs) ----------------
__device__ float g_xyz[BATCH * NPTS1 * 3];                       // 3 MB
__device__ float g_newxyz1[BATCH * M1 * 3];
__device__ float g_newxyz2[BATCH * M2 * 3];
__device__ int   g_ball1[BATCH * M1 * KNN1];                     // 2 MB
__device__ int   g_ball2[BATCH * M2 * KNN2];                     // 1 MB
// grouped input: max(524288*3, 262144*131) = 34,340,864 floats (~137 MB)
__device__ float g_grouped[34340864];
__device__ float g_bufA[33554432];                               // 134 MB (524288*64 / 262144*128 / 4096*256)
__device__ float g_bufB[33554432];                               // 134 MB
__device__ float g_bufC[67108864];                               // 268 MB (524288*128 / 262144*256 / 4096*1024)
__device__ float g_feats1[BATCH * M1 * 128];                     // 8 MB
__device__ float g_feats2[BATCH * M2 * 256];                     // 4 MB
__device__ float g_pool[BATCH * 1024];
__device__ float g_g1[BATCH * 512];
__device__ float g_g2[BATCH * 256];

// ---------------- transpose [B,3,N] -> [B,N,3] ----------------
__global__ void k_transpose(const float* __restrict__ pts) {
    int idx = blockIdx.x * blockDim.x + threadIdx.x;
    if (idx >= BATCH * 3 * NPTS1) return;
    int b = idx / (3 * NPTS1);
    int r = idx % (3 * NPTS1);
    int c = r / NPTS1;
    int n = r % NPTS1;
    g_xyz[(b * NPTS1 + n) * 3 + c] = pts[idx];
}

// ---------------- farthest point sampling ----------------
// One block per batch. P points per thread held in registers; layout i = j*T + tid.
// Matches jnp: dists init 1e10, start at index 0, argmax first-occurrence tie-break.
template <int P, int NP, int MSEL>
__global__ void k_fps(const float* __restrict__ xyz, float* __restrict__ new_xyz) {
    int b = blockIdx.x, tid = threadIdx.x, T = blockDim.x;
    float px[P], py[P], pz[P], pd[P];
#pragma unroll
    for (int j = 0; j < P; j++) {
        int i = j * T + tid;
        const float* p = &xyz[(b * NP + i) * 3];
        px[j] = p[0]; py[j] = p[1]; pz[j] = p[2];
        pd[j] = 1e10f;
    }
    __shared__ float s_cx, s_cy, s_cz;
    __shared__ float s_val[32];
    __shared__ int   s_idx[32];
    if (tid == 0) {
        const float* p = &xyz[(size_t)b * NP * 3];
        s_cx = p[0]; s_cy = p[1]; s_cz = p[2];
        float* o = &new_xyz[(size_t)b * MSEL * 3];
        o[0] = p[0]; o[1] = p[1]; o[2] = p[2];
    }
    __syncthreads();

    int nw = T >> 5;
    for (int it = 1; it < MSEL; it++) {
        float cx = s_cx, cy = s_cy, cz = s_cz;
        float bv = -1.0f; int bi = NP;
#pragma unroll
        for (int j = 0; j < P; j++) {
            int i = j * T + tid;
            float dx = px[j] - cx, dy = py[j] - cy, dz = pz[j] - cz;
            float d = fmaf(dz, dz, fmaf(dy, dy, dx * dx));
            d = fminf(pd[j], d);
            pd[j] = d;
            if (d > bv || (d == bv && i < bi)) { bv = d; bi = i; }
        }
#pragma unroll
        for (int off = 16; off > 0; off >>= 1) {
            float ov = __shfl_down_sync(0xffffffffu, bv, off);
            int   oi = __shfl_down_sync(0xffffffffu, bi, off);
            if (ov > bv || (ov == bv && oi < bi)) { bv = ov; bi = oi; }
        }
        int w = tid >> 5;
        if ((tid & 31) == 0) { s_val[w] = bv; s_idx[w] = bi; }
        __syncthreads();
        if (w == 0) {
            int lane = tid & 31;
            bv = (lane < nw) ? s_val[lane] : -2.0f;
            bi = (lane < nw) ? s_idx[lane] : NP;
#pragma unroll
            for (int off = 16; off > 0; off >>= 1) {
                float ov = __shfl_down_sync(0xffffffffu, bv, off);
                int   oi = __shfl_down_sync(0xffffffffu, bi, off);
                if (ov > bv || (ov == bv && oi < bi)) { bv = ov; bi = oi; }
            }
            if (lane == 0) {
                const float* p = &xyz[((size_t)b * NP + bi) * 3];
                float qx = p[0], qy = p[1], qz = p[2];
                s_cx = qx; s_cy = qy; s_cz = qz;
                float* o = &new_xyz[((size_t)b * MSEL + it) * 3];
                o[0] = qx; o[1] = qy; o[2] = qz;
            }
        }
        __syncthreads();
    }
}

// ---------------- ball query: first-K in-radius indices, padded with first hit ----------------
// Warp per centroid; full scan (no early exit -> loads pipeline), writes guarded by pos<K.
template <int NP, int MSEL, int KQ>
__global__ void k_ballquery(const float* __restrict__ xyz, const float* __restrict__ cent,
                            float R2, int* __restrict__ out) {
    int gw = (blockIdx.x * blockDim.x + threadIdx.x) >> 5;
    int lane = threadIdx.x & 31;
    if (gw >= BATCH * MSEL) return;
    int b = gw / MSEL, m = gw % MSEL;
    const float* cp = &cent[((size_t)b * MSEL + m) * 3];
    float cx = cp[0], cy = cp[1], cz = cp[2];
    const float* xb = &xyz[(size_t)b * NP * 3];
    int* o = &out[((size_t)b * MSEL + m) * KQ];
    int cnt = 0, first = -1;
#pragma unroll 4
    for (int base = 0; base < NP; base += 32) {
        int i = base + lane;
        const float* p = &xb[i * 3];
        float dx = p[0] - cx, dy = p[1] - cy, dz = p[2] - cz;
        float d = fmaf(dz, dz, fmaf(dy, dy, dx * dx));
        bool valid = d < R2;
        unsigned mk = __ballot_sync(0xffffffffu, valid);
        if (first < 0 && mk) first = base + __ffs(mk) - 1;
        int pos = cnt + __popc(mk & ((1u << lane) - 1u));
        if (valid && pos < KQ) o[pos] = i;
        cnt += __popc(mk);
    }
    if (cnt > KQ) cnt = KQ;
    for (int p = cnt + lane; p < KQ; p += 32) o[p] = first;
}

// ---------------- SA1 grouping: relative xyz only ----------------
__global__ void k_group1() {
    int r = blockIdx.x * blockDim.x + threadIdx.x;  // B*M1*KNN1 rows
    if (r >= BATCH * M1 * KNN1) return;
    int g = r / KNN1;
    int b = g / M1;
    int i = g_ball1[r];
    const float* p = &g_xyz[((size_t)b * NPTS1 + i) * 3];
    const float* c = &g_newxyz1[(size_t)g * 3];
    float* o = &g_grouped[(size_t)r * 3];
    o[0] = p[0] - c[0]; o[1] = p[1] - c[1]; o[2] = p[2] - c[2];
}

// ---------------- SA2 grouping: rel xyz (3) + SA1 feats (128) = 131 ch ----------------
__global__ void k_group2() {
    int gw = (blockIdx.x * blockDim.x + threadIdx.x) >> 5;
    int lane = threadIdx.x & 31;
    if (gw >= BATCH * M2 * KNN2) return;
    int g = gw / KNN2;
    int b = g / M2;
    int i = g_ball2[gw];
    float* o = &g_grouped[(size_t)gw * 131];
    const float* c = &g_newxyz2[(size_t)g * 3];
    const float* p = &g_newxyz1[((size_t)b * NPTS2 + i) * 3];
    if (lane < 3) o[lane] = p[lane] - c[lane];
    const float* f = &g_feats1[((size_t)b * NPTS2 + i) * 128];
    for (int c2 = lane; c2 < 128; c2 += 32) o[3 + c2] = f[c2];
}

// ---------------- max over KK consecutive rows ----------------
template <int KK>
__global__ void k_maxk(const float* __restrict__ in, float* __restrict__ out, int G, int C) {
    int idx = blockIdx.x * blockDim.x + threadIdx.x;
    if (idx >= G * C) return;
    int g = idx / C, c = idx % C;
    const float* p = &in[((size_t)g * KK) * C + c];
    float v = p[0];
#pragma unroll 8
    for (int j = 1; j < KK; j++) v = fmaxf(v, p[(size_t)j * C]);
    out[idx] = v;
}

// ---------------- tiled fp32 GEMM: C[M,N] = act(A[M,K] @ W[N,K]^T + bias) ----------------
__global__ void __launch_bounds__(256) k_gemm(const float* __restrict__ A,
                                              const float* __restrict__ W,
                                              const float* __restrict__ bias,
                                              float* __restrict__ C,
                                              int Mm, int Nn, int Kk, int relu) {
    __shared__ float As[8][128];
    __shared__ float Bs[8][128];
    int row0 = blockIdx.y * 128, col0 = blockIdx.x * 128;
    int t = threadIdx.x;
    int tx = t & 15, ty = t >> 4;
    float acc[8][8];
#pragma unroll
    for (int i = 0; i < 8; i++)
#pragma unroll
        for (int j = 0; j < 8; j++) acc[i][j] = 0.f;

    for (int k0 = 0; k0 < Kk; k0 += 8) {
#pragma unroll
        for (int q = 0; q < 4; q++) {
            int e = t * 4 + q;
            int rr = e >> 3, kk = e & 7;
            int gr = row0 + rr, gk = k0 + kk;
            As[kk][rr] = (gr < Mm && gk < Kk) ? A[(size_t)gr * Kk + gk] : 0.f;
            int gc = col0 + rr;
            Bs[kk][rr] = (gc < Nn && gk < Kk) ? W[(size_t)gc * Kk + gk] : 0.f;
        }
        __syncthreads();
#pragma unroll
        for (int kk = 0; kk < 8; kk++) {
            float a[8], bb[8];
#pragma unroll
            for (int i = 0; i < 8; i++) {
                a[i]  = As[kk][ty + i * 16];
                bb[i] = Bs[kk][tx + i * 16];
            }
#pragma unroll
            for (int i = 0; i < 8; i++)
#pragma unroll
                for (int j = 0; j < 8; j++) acc[i][j] = fmaf(a[i], bb[j], acc[i][j]);
        }
        __syncthreads();
    }
#pragma unroll
    for (int i = 0; i < 8; i++) {
        int r = row0 + ty + i * 16;
        if (r >= Mm) continue;
#pragma unroll
        for (int j = 0; j < 8; j++) {
            int c = col0 + tx + j * 16;
            if (c >= Nn) continue;
            float v = acc[i][j] + bias[c];
            if (relu) v = fmaxf(v, 0.f);
            C[(size_t)r * Nn + c] = v;
        }
    }
}

// ---------------- host-side launch ----------------
static void* sym_addr(const void* sym) {
    void* p = nullptr;
    cudaGetSymbolAddress(&p, sym);
    return p;
}

static inline void gemm(const float* A, const float* W, const float* b, float* C,
                        int M, int N, int K, int relu) {
    dim3 grid((N + 127) / 128, (M + 127) / 128);
    k_gemm<<<grid, 256>>>(A, W, b, C, M, N, K, relu);
}

extern "C" void kernel_launch(void* const* d_in, const int* in_sizes, int n_in,
                              void* d_out, int out_size) {
    const float* pts = (const float*)d_in[0];
    const float* sa1w0 = (const float*)d_in[1];  const float* sa1b0 = (const float*)d_in[2];
    const float* sa1w1 = (const float*)d_in[3];  const float* sa1b1 = (const float*)d_in[4];
    const float* sa1w2 = (const float*)d_in[5];  const float* sa1b2 = (const float*)d_in[6];
    const float* sa2w0 = (const float*)d_in[7];  const float* sa2b0 = (const float*)d_in[8];
    const float* sa2w1 = (const float*)d_in[9];  const float* sa2b1 = (const float*)d_in[10];
    const float* sa2w2 = (const float*)d_in[11]; const float* sa2b2 = (const float*)d_in[12];
    const float* locw0 = (const float*)d_in[13]; const float* locb0 = (const float*)d_in[14];
    const float* locw1 = (const float*)d_in[15]; const float* locb1 = (const float*)d_in[16];
    const float* locw2 = (const float*)d_in[17]; const float* locb2 = (const float*)d_in[18];
    const float* glow0 = (const float*)d_in[19]; const float* glob0 = (const float*)d_in[20];
    const float* glow1 = (const float*)d_in[21]; const float* glob1 = (const float*)d_in[22];
    const float* clsw  = (const float*)d_in[23]; const float* clsb  = (const float*)d_in[24];
    float* out = (float*)d_out;

    float* xyz     = (float*)sym_addr(g_xyz);
    float* nx1     = (float*)sym_addr(g_newxyz1);
    float* nx2     = (float*)sym_addr(g_newxyz2);
    int*   ball1   = (int*)  sym_addr(g_ball1);
    int*   ball2   = (int*)  sym_addr(g_ball2);
    float* grouped = (float*)sym_addr(g_grouped);
    float* bufA    = (float*)sym_addr(g_bufA);
    float* bufB    = (float*)sym_addr(g_bufB);
    float* bufC    = (float*)sym_addr(g_bufC);
    float* feats1  = (float*)sym_addr(g_feats1);
    float* feats2  = (float*)sym_addr(g_feats2);
    float* pool    = (float*)sym_addr(g_pool);
    float* gg1     = (float*)sym_addr(g_g1);
    float* gg2     = (float*)sym_addr(g_g2);

    // radii squared, computed exactly as JAX does: python double (r*r) rounded to f32
    const float R2_1 = (float)(0.2 * 0.2);
    const float R2_2 = (float)(0.4 * 0.4);

    // 1. transpose points
    k_transpose<<<(BATCH * 3 * NPTS1 + 255) / 256, 256>>>(pts);

    // 2. SA1: FPS -> ball query -> group -> MLP(3,64,64,128) -> max over 32
    k_fps<8, NPTS1, M1><<<BATCH, 1024>>>(xyz, nx1);
    k_ballquery<NPTS1, M1, KNN1><<<(BATCH * M1) / 8, 256>>>(xyz, nx1, R2_1, ball1);
    k_group1<<<(BATCH * M1 * KNN1 + 255) / 256, 256>>>();
    gemm(grouped, sa1w0, sa1b0, bufA, BATCH * M1 * KNN1, 64, 3, 1);
    gemm(bufA,    sa1w1, sa1b1, bufB, BATCH * M1 * KNN1, 64, 64, 1);
    gemm(bufB,    sa1w2, sa1b2, bufC, BATCH * M1 * KNN1, 128, 64, 1);
    k_maxk<KNN1><<<(BATCH * M1 * 128 + 255) / 256, 256>>>(bufC, feats1, BATCH * M1, 128);

    // 3. SA2: FPS -> ball query -> group(3+128) -> MLP(131,128,128,256) -> max over 64
    k_fps<1, NPTS2, M2><<<BATCH, 512>>>(nx1, nx2);
    k_ballquery<NPTS2, M2, KNN2><<<(BATCH * M2) / 8, 256>>>(nx1, nx2, R2_2, ball2);
    k_group2<<<(BATCH * M2 * KNN2 * 32 + 255) / 256, 256>>>();
    gemm(grouped, sa2w0, sa2b0, bufA, BATCH * M2 * KNN2, 128, 131, 1);
    gemm(bufA,    sa2w1, sa2b1, bufB, BATCH * M2 * KNN2, 128, 128, 1);
    gemm(bufB,    sa2w2, sa2b2, bufC, BATCH * M2 * KNN2, 256, 128, 1);
    k_maxk<KNN2><<<(BATCH * M2 * 256 + 255) / 256, 256>>>(bufC, feats2, BATCH * M2, 256);

    // 4. loc shared-MLP 256 -> 256 -> 512 -> 1024 over B*128 points, then max over points
    gemm(feats2, locw0, locb0, bufA, BATCH * M2, 256, 256, 1);
    gemm(bufA,   locw1, locb1, bufB, BATCH * M2, 512, 256, 1);
    gemm(bufB,   locw2, locb2, bufC, BATCH * M2, 1024, 512, 1);
    k_maxk<M2><<<(BATCH * 1024 + 255) / 256, 256>>>(bufC, pool, BATCH, 1024);

    // 5. global MLP 1024 -> 512 -> 256 -> 40 (last layer no relu)
    gemm(pool, glow0, glob0, gg1, BATCH, 512, 1024, 1);
    gemm(gg1,  glow1, glob1, gg2, BATCH, 256, 512, 1);
    gemm(gg2,  clsw,  clsb,  out, BATCH, 40, 256, 0);
}

// round 3
// speedup vs baseline: 1.1149x; 1.1149x over previous
#include <cuda_runtime.h>
#include <cstddef>

#define BATCH 32
#define NPTS1 8192
#define M1 512
#define KNN1 32
#define M2 128
#define KNN2 64
#define NPTS2 512

// ---------------- scratch (static device globals; no allocs) ----------------
__device__ float g_xyz[BATCH * NPTS1 * 3];
__device__ float g_newxyz1[BATCH * M1 * 3];
__device__ float g_newxyz2[BATCH * M2 * 3];
__device__ int   g_ball1[BATCH * M1 * KNN1];
__device__ int   g_ball2[BATCH * M2 * KNN2];
__device__ float g_grouped[34340864];   // max(524288*3, 262144*131)
__device__ float g_bufA[33554432];
__device__ float g_bufB[33554432];
__device__ float g_feats1[BATCH * M1 * 128];
__device__ float g_feats2[BATCH * M2 * 256];
__device__ float g_pool[BATCH * 1024];
__device__ float g_g1[BATCH * 512];
__device__ float g_g2[BATCH * 256];

// ---------------- f32x2 helpers ----------------
__device__ __forceinline__ void fma2(unsigned long long& c, unsigned long long a, unsigned long long b) {
    asm("fma.rn.f32x2 %0, %1, %2, %0;" : "+l"(c) : "l"(a), "l"(b));
}
__device__ __forceinline__ float2 unpk(unsigned long long v) {
    float2 r; asm("mov.b64 {%0, %1}, %2;" : "=f"(r.x), "=f"(r.y) : "l"(v)); return r;
}

// ---------------- transpose [B,3,N] -> [B,N,3] ----------------
__global__ void k_transpose(const float* __restrict__ pts) {
    int idx = blockIdx.x * blockDim.x + threadIdx.x;
    if (idx >= BATCH * 3 * NPTS1) return;
    int b = idx / (3 * NPTS1);
    int r = idx % (3 * NPTS1);
    int c = r / NPTS1;
    int n = r % NPTS1;
    g_xyz[(b * NPTS1 + n) * 3 + c] = pts[idx];
}

// ---------------- farthest point sampling ----------------
template <int P, int NP, int MSEL>
__global__ void k_fps(const float* __restrict__ xyz, float* __restrict__ new_xyz) {
    int b = blockIdx.x, tid = threadIdx.x, T = blockDim.x;
    float px[P], py[P], pz[P], pd[P];
#pragma unroll
    for (int j = 0; j < P; j++) {
        int i = j * T + tid;
        const float* p = &xyz[(b * NP + i) * 3];
        px[j] = p[0]; py[j] = p[1]; pz[j] = p[2];
        pd[j] = 1e10f;
    }
    __shared__ float s_cx, s_cy, s_cz;
    __shared__ float s_val[32];
    __shared__ int   s_idx[32];
    if (tid == 0) {
        const float* p = &xyz[(size_t)b * NP * 3];
        s_cx = p[0]; s_cy = p[1]; s_cz = p[2];
        float* o = &new_xyz[(size_t)b * MSEL * 3];
        o[0] = p[0]; o[1] = p[1]; o[2] = p[2];
    }
    __syncthreads();

    int nw = T >> 5;
    for (int it = 1; it < MSEL; it++) {
        float cx = s_cx, cy = s_cy, cz = s_cz;
        float bv = -1.0f; int bi = NP;
#pragma unroll
        for (int j = 0; j < P; j++) {
            int i = j * T + tid;
            float dx = px[j] - cx, dy = py[j] - cy, dz = pz[j] - cz;
            float d = fmaf(dz, dz, fmaf(dy, dy, dx * dx));
            d = fminf(pd[j], d);
            pd[j] = d;
            if (d > bv || (d == bv && i < bi)) { bv = d; bi = i; }
        }
#pragma unroll
        for (int off = 16; off > 0; off >>= 1) {
            float ov = __shfl_down_sync(0xffffffffu, bv, off);
            int   oi = __shfl_down_sync(0xffffffffu, bi, off);
            if (ov > bv || (ov == bv && oi < bi)) { bv = ov; bi = oi; }
        }
        int w = tid >> 5;
        if ((tid & 31) == 0) { s_val[w] = bv; s_idx[w] = bi; }
        __syncthreads();
        if (w == 0) {
            int lane = tid & 31;
            bv = (lane < nw) ? s_val[lane] : -2.0f;
            bi = (lane < nw) ? s_idx[lane] : NP;
#pragma unroll
            for (int off = 16; off > 0; off >>= 1) {
                float ov = __shfl_down_sync(0xffffffffu, bv, off);
                int   oi = __shfl_down_sync(0xffffffffu, bi, off);
                if (ov > bv || (ov == bv && oi < bi)) { bv = ov; bi = oi; }
            }
            if (lane == 0) {
                const float* p = &xyz[((size_t)b * NP + bi) * 3];
                float qx = p[0], qy = p[1], qz = p[2];
                s_cx = qx; s_cy = qy; s_cz = qz;
                float* o = &new_xyz[((size_t)b * MSEL + it) * 3];
                o[0] = qx; o[1] = qy; o[2] = qz;
            }
        }
        __syncthreads();
    }
}

// ---------------- ball query ----------------
template <int NP, int MSEL, int KQ>
__global__ void k_ballquery(const float* __restrict__ xyz, const float* __restrict__ cent,
                            float R2, int* __restrict__ out) {
    int gw = (blockIdx.x * blockDim.x + threadIdx.x) >> 5;
    int lane = threadIdx.x & 31;
    if (gw >= BATCH * MSEL) return;
    int b = gw / MSEL, m = gw % MSEL;
    const float* cp = &cent[((size_t)b * MSEL + m) * 3];
    float cx = cp[0], cy = cp[1], cz = cp[2];
    const float* xb = &xyz[(size_t)b * NP * 3];
    int* o = &out[((size_t)b * MSEL + m) * KQ];
    int cnt = 0, first = -1;
#pragma unroll 4
    for (int base = 0; base < NP; base += 32) {
        int i = base + lane;
        const float* p = &xb[i * 3];
        float dx = p[0] - cx, dy = p[1] - cy, dz = p[2] - cz;
        float d = fmaf(dz, dz, fmaf(dy, dy, dx * dx));
        bool valid = d < R2;
        unsigned mk = __ballot_sync(0xffffffffu, valid);
        if (first < 0 && mk) first = base + __ffs(mk) - 1;
        int pos = cnt + __popc(mk & ((1u << lane) - 1u));
        if (valid && pos < KQ) o[pos] = i;
        cnt += __popc(mk);
    }
    if (cnt > KQ) cnt = KQ;
    for (int p = cnt + lane; p < KQ; p += 32) o[p] = first;
}

// ---------------- grouping ----------------
__global__ void k_group1() {
    int r = blockIdx.x * blockDim.x + threadIdx.x;
    if (r >= BATCH * M1 * KNN1) return;
    int g = r / KNN1;
    int b = g / M1;
    int i = g_ball1[r];
    const float* p = &g_xyz[((size_t)b * NPTS1 + i) * 3];
    const float* c = &g_newxyz1[(size_t)g * 3];
    float* o = &g_grouped[(size_t)r * 3];
    o[0] = p[0] - c[0]; o[1] = p[1] - c[1]; o[2] = p[2] - c[2];
}

__global__ void k_group2() {
    int gw = (blockIdx.x * blockDim.x + threadIdx.x) >> 5;
    int lane = threadIdx.x & 31;
    if (gw >= BATCH * M2 * KNN2) return;
    int g = gw / KNN2;
    int b = g / M2;
    int i = g_ball2[gw];
    float* o = &g_grouped[(size_t)gw * 131];
    const float* c = &g_newxyz2[(size_t)g * 3];
    const float* p = &g_newxyz1[((size_t)b * NPTS2 + i) * 3];
    if (lane < 3) o[lane] = p[lane] - c[lane];
    const float* f = &g_feats1[((size_t)b * NPTS2 + i) * 128];
    for (int c2 = lane; c2 < 128; c2 += 32) o[3 + c2] = f[c2];
}

// ---------------- f32x2 tiled GEMM: C = act(A[M,K] @ W[N,K]^T + bias) ----------------
// 128x128 tile, 256 threads, 8x8 microtile as f32x2 pairs, K-chunk 16, double-buffered.
// KNNPOOL > 0: fused relu + max over KNNPOOL consecutive rows (group-aligned tiles),
// output has M/KNNPOOL rows. Requires M%128==0, N%128==0 when pooling.
template <int KNNPOOL>
__global__ void __launch_bounds__(256, 2) k_gemm2(const float* __restrict__ A,
                                                  const float* __restrict__ W,
                                                  const float* __restrict__ bias,
                                                  float* __restrict__ C,
                                                  int Mm, int Nn, int Kk, int relu) {
    __shared__ float As2[2][16][256];   // A duplicated: [kk][2*r+{0,1}] = A[row0+r][k]
    __shared__ float Bs[2][16][128];

    int t = threadIdx.x;
    int tx = t & 15, ty = t >> 4;
    int row0 = blockIdx.y * 128, col0 = blockIdx.x * 128;

    int lrow = t >> 1;          // 0..127
    int lk   = (t & 1) * 8;     // 0 or 8
    bool aok = (row0 + lrow) < Mm;
    bool bok = (col0 + lrow) < Nn;
    const float* Ap = A + (size_t)(row0 + lrow) * Kk;
    const float* Wp = W + (size_t)(col0 + lrow) * Kk;

    unsigned long long acc[8][4];
#pragma unroll
    for (int i = 0; i < 8; i++)
#pragma unroll
        for (int j = 0; j < 4; j++) acc[i][j] = 0ull;

    int nchunks = (Kk + 15) / 16;

    // prologue: chunk 0
    {
        float av[8], bv[8];
#pragma unroll
        for (int q = 0; q < 8; q++) {
            int k = lk + q;
            av[q] = (aok && k < Kk) ? Ap[k] : 0.f;
            bv[q] = (bok && k < Kk) ? Wp[k] : 0.f;
        }
#pragma unroll
        for (int q = 0; q < 8; q++) {
            *(float2*)&As2[0][lk + q][2 * lrow] = make_float2(av[q], av[q]);
            Bs[0][lk + q][lrow] = bv[q];
        }
    }
    __syncthreads();

    for (int c = 0; c < nchunks; c++) {
        int buf = c & 1;
        float av[8], bv[8];
        bool more = (c + 1) < nchunks;
        if (more) {
            int k0 = (c + 1) * 16;
#pragma unroll
            for (int q = 0; q < 8; q++) {
                int k = k0 + lk + q;
                av[q] = (aok && k < Kk) ? Ap[k] : 0.f;
                bv[q] = (bok && k < Kk) ? Wp[k] : 0.f;
            }
        }
#pragma unroll
        for (int kk = 0; kk < 16; kk++) {
            const float* arow = As2[buf][kk];
            const float* brow = Bs[buf][kk];
            ulonglong2 aA = *(const ulonglong2*)(arow + ty * 8);
            ulonglong2 aB = *(const ulonglong2*)(arow + ty * 8 + 4);
            ulonglong2 aC = *(const ulonglong2*)(arow + 128 + ty * 8);
            ulonglong2 aD = *(const ulonglong2*)(arow + 128 + ty * 8 + 4);
            ulonglong2 b01 = *(const ulonglong2*)(brow + tx * 4);
            ulonglong2 b23 = *(const ulonglong2*)(brow + 64 + tx * 4);
            unsigned long long ar[8] = {aA.x, aA.y, aB.x, aB.y, aC.x, aC.y, aD.x, aD.y};
            unsigned long long br[4] = {b01.x, b01.y, b23.x, b23.y};
#pragma unroll
            for (int i = 0; i < 8; i++)
#pragma unroll
                for (int j = 0; j < 4; j++) fma2(acc[i][j], ar[i], br[j]);
        }
        if (more) {
            int nb = buf ^ 1;
#pragma unroll
            for (int q = 0; q < 8; q++) {
                *(float2*)&As2[nb][lk + q][2 * lrow] = make_float2(av[q], av[q]);
                Bs[nb][lk + q][lrow] = bv[q];
            }
        }
        __syncthreads();
    }

    if (KNNPOOL == 0) {
#pragma unroll
        for (int blk = 0; blk < 2; blk++) {
#pragma unroll
            for (int i = 0; i < 4; i++) {
                int r = row0 + blk * 64 + ty * 4 + i;
                if (r >= Mm) continue;
#pragma unroll
                for (int jp = 0; jp < 4; jp++) {
                    float2 v = unpk(acc[blk * 4 + i][jp]);
                    int cc = col0 + (jp >> 1) * 64 + tx * 4 + (jp & 1) * 2;
                    if (cc < Nn) {
                        float x = v.x + bias[cc];
                        if (relu) x = fmaxf(x, 0.f);
                        C[(size_t)r * Nn + cc] = x;
                    }
                    if (cc + 1 < Nn) {
                        float x = v.y + bias[cc + 1];
                        if (relu) x = fmaxf(x, 0.f);
                        C[(size_t)r * Nn + cc + 1] = x;
                    }
                }
            }
        }
    } else {
        // fused relu + max-pool over KNNPOOL rows (always relu). Exact tiles assumed.
        const int NG = 128 / KNNPOOL;
        int* sred = (int*)&As2[0][0][0];
        for (int i = t; i < NG * 128; i += 256) sred[i] = 0;
        __syncthreads();
#pragma unroll
        for (int blk = 0; blk < 2; blk++) {
            int gl = (blk * 64 + ty * 4) / KNNPOOL;
#pragma unroll
            for (int jp = 0; jp < 4; jp++) {
                int lc = (jp >> 1) * 64 + tx * 4 + (jp & 1) * 2;
                float b0 = bias[col0 + lc], b1 = bias[col0 + lc + 1];
                float m0 = -1e30f, m1 = -1e30f;
#pragma unroll
                for (int i = 0; i < 4; i++) {
                    float2 v = unpk(acc[blk * 4 + i][jp]);
                    m0 = fmaxf(m0, v.x);
                    m1 = fmaxf(m1, v.y);
                }
                m0 = fmaxf(m0 + b0, 0.f);
                m1 = fmaxf(m1 + b1, 0.f);
                atomicMax(&sred[gl * 128 + lc], __float_as_int(m0));
                atomicMax(&sred[gl * 128 + lc + 1], __float_as_int(m1));
            }
        }
        __syncthreads();
        for (int i = t; i < NG * 128; i += 256) {
            int gl = i >> 7, lc = i & 127;
            C[(size_t)(row0 / KNNPOOL + gl) * Nn + col0 + lc] = __int_as_float(sred[i]);
        }
    }
}

// ---------------- host-side launch ----------------
static void* sym_addr(const void* sym) {
    void* p = nullptr;
    cudaGetSymbolAddress(&p, sym);
    return p;
}

static inline void gemm(const float* A, const float* W, const float* b, float* C,
                        int M, int N, int K, int relu) {
    dim3 grid((N + 127) / 128, (M + 127) / 128);
    k_gemm2<0><<<grid, 256>>>(A, W, b, C, M, N, K, relu);
}
template <int KNN>
static inline void gemm_pool(const float* A, const float* W, const float* b, float* C,
                             int M, int N, int K) {
    dim3 grid(N / 128, M / 128);
    k_gemm2<KNN><<<grid, 256>>>(A, W, b, C, M, N, K, 1);
}

extern "C" void kernel_launch(void* const* d_in, const int* in_sizes, int n_in,
                              void* d_out, int out_size) {
    const float* pts = (const float*)d_in[0];
    const float* sa1w0 = (const float*)d_in[1];  const float* sa1b0 = (const float*)d_in[2];
    const float* sa1w1 = (const float*)d_in[3];  const float* sa1b1 = (const float*)d_in[4];
    const float* sa1w2 = (const float*)d_in[5];  const float* sa1b2 = (const float*)d_in[6];
    const float* sa2w0 = (const float*)d_in[7];  const float* sa2b0 = (const float*)d_in[8];
    const float* sa2w1 = (const float*)d_in[9];  const float* sa2b1 = (const float*)d_in[10];
    const float* sa2w2 = (const float*)d_in[11]; const float* sa2b2 = (const float*)d_in[12];
    const float* locw0 = (const float*)d_in[13]; const float* locb0 = (const float*)d_in[14];
    const float* locw1 = (const float*)d_in[15]; const float* locb1 = (const float*)d_in[16];
    const float* locw2 = (const float*)d_in[17]; const float* locb2 = (const float*)d_in[18];
    const float* glow0 = (const float*)d_in[19]; const float* glob0 = (const float*)d_in[20];
    const float* glow1 = (const float*)d_in[21]; const float* glob1 = (const float*)d_in[22];
    const float* clsw  = (const float*)d_in[23]; const float* clsb  = (const float*)d_in[24];
    float* out = (float*)d_out;

    float* xyz     = (float*)sym_addr(g_xyz);
    float* nx1     = (float*)sym_addr(g_newxyz1);
    float* nx2     = (float*)sym_addr(g_newxyz2);
    int*   ball1   = (int*)  sym_addr(g_ball1);
    int*   ball2   = (int*)  sym_addr(g_ball2);
    float* grouped = (float*)sym_addr(g_grouped);
    float* bufA    = (float*)sym_addr(g_bufA);
    float* bufB    = (float*)sym_addr(g_bufB);
    float* feats1  = (float*)sym_addr(g_feats1);
    float* feats2  = (float*)sym_addr(g_feats2);
    float* pool    = (float*)sym_addr(g_pool);
    float* gg1     = (float*)sym_addr(g_g1);
    float* gg2     = (float*)sym_addr(g_g2);

    const float R2_1 = (float)(0.2 * 0.2);
    const float R2_2 = (float)(0.4 * 0.4);

    // 1. transpose
    k_transpose<<<(BATCH * 3 * NPTS1 + 255) / 256, 256>>>(pts);

    // 2. SA1
    k_fps<8, NPTS1, M1><<<BATCH, 1024>>>(xyz, nx1);
    k_ballquery<NPTS1, M1, KNN1><<<(BATCH * M1) / 8, 256>>>(xyz, nx1, R2_1, ball1);
    k_group1<<<(BATCH * M1 * KNN1 + 255) / 256, 256>>>();
    gemm(grouped, sa1w0, sa1b0, bufA, BATCH * M1 * KNN1, 64, 3, 1);
    gemm(bufA,    sa1w1, sa1b1, bufB, BATCH * M1 * KNN1, 64, 64, 1);
    gemm_pool<KNN1>(bufB, sa1w2, sa1b2, feats1, BATCH * M1 * KNN1, 128, 64);

    // 3. SA2
    k_fps<1, NPTS2, M2><<<BATCH, 512>>>(nx1, nx2);
    k_ballquery<NPTS2, M2, KNN2><<<(BATCH * M2) / 8, 256>>>(nx1, nx2, R2_2, ball2);
    k_group2<<<(BATCH * M2 * KNN2 * 32 + 255) / 256, 256>>>();
    gemm(grouped, sa2w0, sa2b0, bufA, BATCH * M2 * KNN2, 128, 131, 1);
    gemm(bufA,    sa2w1, sa2b1, bufB, BATCH * M2 * KNN2, 128, 128, 1);
    gemm_pool<KNN2>(bufB, sa2w2, sa2b2, feats2, BATCH * M2 * KNN2, 256, 128);

    // 4. loc MLP + global max-pool (pool over the 128 points = one tile)
    gemm(feats2, locw0, locb0, bufA, BATCH * M2, 256, 256, 1);
    gemm(bufA,   locw1, locb1, bufB, BATCH * M2, 512, 256, 1);
    gemm_pool<128>(bufB, locw2, locb2, pool, BATCH * M2, 1024, 512);

    // 5. global MLP
    gemm(pool, glow0, glob0, gg1, BATCH, 512, 1024, 1);
    gemm(gg1,  glow1, glob1, gg2, BATCH, 256, 512, 1);
    gemm(gg2,  clsw,  clsb,  out, BATCH, 40, 256, 0);
}

// round 8
// speedup vs baseline: 1.4050x; 1.2602x over previous
#include <cuda_runtime.h>
#include <cuda_bf16.h>
#include <cstdint>
#include <cstddef>

#define BATCH 32
#define NPTS1 8192
#define M1 512
#define KNN1 32
#define M2 128
#define KNN2 64
#define NPTS2 512

// ---------------- scratch ----------------
__device__ float g_xyz[BATCH * NPTS1 * 3];
__device__ float g_newxyz1[BATCH * M1 * 3];
__device__ float g_newxyz2[BATCH * M2 * 3];
__device__ int   g_ball1[BATCH * M1 * KNN1];
__device__ int   g_ball2[BATCH * M2 * KNN2];
__device__ float g_grouped[34340864];
__device__ float g_bufA[33554432];
__device__ float g_bufB[33554432];
__device__ float g_feats1[BATCH * M1 * 128];
__device__ float g_feats2[BATCH * M2 * 256];
__device__ float g_pool[BATCH * 1024];
__device__ float g_g1[BATCH * 512];
__device__ float g_g2[BATCH * 256];

// ---------------- helpers ----------------
__device__ __forceinline__ uint32_t smem_u32(const void* p) {
    uint32_t a;
    asm("{ .reg .u64 t; cvta.to.shared.u64 t, %1; cvt.u32.u64 %0, t; }" : "=r"(a) : "l"(p));
    return a;
}
__device__ __forceinline__ void ldmx4(uint32_t* r, uint32_t a) {
    asm volatile("ldmatrix.sync.aligned.m8n8.x4.shared.b16 {%0,%1,%2,%3}, [%4];"
                 : "=r"(r[0]), "=r"(r[1]), "=r"(r[2]), "=r"(r[3]) : "r"(a));
}
__device__ __forceinline__ void mma16816(float* c, const uint32_t* a, const uint32_t* b) {
    asm volatile("mma.sync.aligned.m16n8k16.row.col.f32.bf16.bf16.f32 "
                 "{%0,%1,%2,%3}, {%4,%5,%6,%7}, {%8,%9}, {%0,%1,%2,%3};"
                 : "+f"(c[0]), "+f"(c[1]), "+f"(c[2]), "+f"(c[3])
                 : "r"(a[0]), "r"(a[1]), "r"(a[2]), "r"(a[3]), "r"(b[0]), "r"(b[1]));
}
__device__ __forceinline__ uint32_t pack_bf(__nv_bfloat16 a, __nv_bfloat16 b) {
    return ((uint32_t)__bfloat16_as_ushort(b) << 16) | __bfloat16_as_ushort(a);
}
// convert 8 f32 -> 8 bf16 hi + 8 bf16 lo (packed as uint4 each)
__device__ __forceinline__ void cvt8(const float* v, uint4& hi, uint4& lo) {
    uint32_t h[4], l[4];
#pragma unroll
    for (int q = 0; q < 4; q++) {
        float a0 = v[2 * q], a1 = v[2 * q + 1];
        __nv_bfloat16 h0 = __float2bfloat16(a0), h1 = __float2bfloat16(a1);
        __nv_bfloat16 l0 = __float2bfloat16(a0 - __bfloat162float(h0));
        __nv_bfloat16 l1 = __float2bfloat16(a1 - __bfloat162float(h1));
        h[q] = pack_bf(h0, h1); l[q] = pack_bf(l0, l1);
    }
    hi = make_uint4(h[0], h[1], h[2], h[3]);
    lo = make_uint4(l[0], l[1], l[2], l[3]);
}

// ---------------- transpose ----------------
__global__ void k_transpose(const float* __restrict__ pts) {
    int idx = blockIdx.x * blockDim.x + threadIdx.x;
    if (idx >= BATCH * 3 * NPTS1) return;
    int b = idx / (3 * NPTS1);
    int r = idx % (3 * NPTS1);
    int c = r / NPTS1;
    int n = r % NPTS1;
    g_xyz[(b * NPTS1 + n) * 3 + c] = pts[idx];
}

// ---------------- farthest point sampling ----------------
template <int P, int NP, int MSEL>
__global__ void k_fps(const float* __restrict__ xyz, float* __restrict__ new_xyz) {
    int b = blockIdx.x, tid = threadIdx.x, T = blockDim.x;
    float px[P], py[P], pz[P], pd[P];
#pragma unroll
    for (int j = 0; j < P; j++) {
        int i = j * T + tid;
        const float* p = &xyz[(b * NP + i) * 3];
        px[j] = p[0]; py[j] = p[1]; pz[j] = p[2];
        pd[j] = 1e10f;
    }
    __shared__ float s_cx, s_cy, s_cz;
    __shared__ float s_val[32];
    __shared__ int   s_idx[32];
    if (tid == 0) {
        const float* p = &xyz[(size_t)b * NP * 3];
        s_cx = p[0]; s_cy = p[1]; s_cz = p[2];
        float* o = &new_xyz[(size_t)b * MSEL * 3];
        o[0] = p[0]; o[1] = p[1]; o[2] = p[2];
    }
    __syncthreads();
    int nw = T >> 5;
    for (int it = 1; it < MSEL; it++) {
        float cx = s_cx, cy = s_cy, cz = s_cz;
        float bv = -1.0f; int bi = NP;
#pragma unroll
        for (int j = 0; j < P; j++) {
            int i = j * T + tid;
            float dx = px[j] - cx, dy = py[j] - cy, dz = pz[j] - cz;
            float d = fmaf(dz, dz, fmaf(dy, dy, dx * dx));
            d = fminf(pd[j], d);
            pd[j] = d;
            if (d > bv || (d == bv && i < bi)) { bv = d; bi = i; }
        }
#pragma unroll
        for (int off = 16; off > 0; off >>= 1) {
            float ov = __shfl_down_sync(0xffffffffu, bv, off);
            int   oi = __shfl_down_sync(0xffffffffu, bi, off);
            if (ov > bv || (ov == bv && oi < bi)) { bv = ov; bi = oi; }
        }
        int w = tid >> 5;
        if ((tid & 31) == 0) { s_val[w] = bv; s_idx[w] = bi; }
        __syncthreads();
        if (w == 0) {
            int lane = tid & 31;
            bv = (lane < nw) ? s_val[lane] : -2.0f;
            bi = (lane < nw) ? s_idx[lane] : NP;
#pragma unroll
            for (int off = 16; off > 0; off >>= 1) {
                float ov = __shfl_down_sync(0xffffffffu, bv, off);
                int   oi = __shfl_down_sync(0xffffffffu, bi, off);
                if (ov > bv || (ov == bv && oi < bi)) { bv = ov; bi = oi; }
            }
            if (lane == 0) {
                const float* p = &xyz[((size_t)b * NP + bi) * 3];
                s_cx = p[0]; s_cy = p[1]; s_cz = p[2];
                float* o = &new_xyz[((size_t)b * MSEL + it) * 3];
                o[0] = p[0]; o[1] = p[1]; o[2] = p[2];
            }
        }
        __syncthreads();
    }
}

// ---------------- ball query ----------------
template <int NP, int MSEL, int KQ>
__global__ void k_ballquery(const float* __restrict__ xyz, const float* __restrict__ cent,
                            float R2, int* __restrict__ out) {
    int gw = (blockIdx.x * blockDim.x + threadIdx.x) >> 5;
    int lane = threadIdx.x & 31;
    if (gw >= BATCH * MSEL) return;
    int b = gw / MSEL, m = gw % MSEL;
    const float* cp = &cent[((size_t)b * MSEL + m) * 3];
    float cx = cp[0], cy = cp[1], cz = cp[2];
    const float* xb = &xyz[(size_t)b * NP * 3];
    int* o = &out[((size_t)b * MSEL + m) * KQ];
    int cnt = 0, first = -1;
#pragma unroll 4
    for (int base = 0; base < NP; base += 32) {
        int i = base + lane;
        const float* p = &xb[i * 3];
        float dx = p[0] - cx, dy = p[1] - cy, dz = p[2] - cz;
        float d = fmaf(dz, dz, fmaf(dy, dy, dx * dx));
        bool valid = d < R2;
        unsigned mk = __ballot_sync(0xffffffffu, valid);
        if (first < 0 && mk) first = base + __ffs(mk) - 1;
        int pos = cnt + __popc(mk & ((1u << lane) - 1u));
        if (valid && pos < KQ) o[pos] = i;
        cnt += __popc(mk);
    }
    if (cnt > KQ) cnt = KQ;
    for (int p = cnt + lane; p < KQ; p += 32) o[p] = first;
}

// ---------------- grouping ----------------
__global__ void k_group1() {
    int r = blockIdx.x * blockDim.x + threadIdx.x;
    if (r >= BATCH * M1 * KNN1) return;
    int g = r / KNN1;
    int b = g / M1;
    int i = g_ball1[r];
    const float* p = &g_xyz[((size_t)b * NPTS1 + i) * 3];
    const float* c = &g_newxyz1[(size_t)g * 3];
    float* o = &g_grouped[(size_t)r * 3];
    o[0] = p[0] - c[0]; o[1] = p[1] - c[1]; o[2] = p[2] - c[2];
}

__global__ void k_group2() {
    int gw = (blockIdx.x * blockDim.x + threadIdx.x) >> 5;
    int lane = threadIdx.x & 31;
    if (gw >= BATCH * M2 * KNN2) return;
    int g = gw / KNN2;
    int b = g / M2;
    int i = g_ball2[gw];
    float* o = &g_grouped[(size_t)gw * 131];
    const float* c = &g_newxyz2[(size_t)g * 3];
    const float* p = &g_newxyz1[((size_t)b * NPTS2 + i) * 3];
    if (lane < 3) o[lane] = p[lane] - c[lane];
    const float* f = &g_feats1[((size_t)b * NPTS2 + i) * 128];
    for (int c2 = lane; c2 < 128; c2 += 32) o[3 + c2] = f[c2];
}

// ============================================================================
// HMMA bf16x3 GEMM: C = relu(A[M,K] @ W[N,K]^T + bias), optional KNN max-pool.
// Tile 128 x BN, 256 threads (8 warps), K-chunk 16.
// A,W split hi/lo bf16; D += Ahi*Bhi + Ahi*Blo + Alo*Bhi (f32 accum).
// Requires: M % 128 == 0, N % BN == 0.
// ============================================================================
#define SM_STRIDE 48          // bytes per smem row (16 bf16 data + pad, conflict-free)
#define OFF_AHI 0
#define OFF_ALO (128 * SM_STRIDE)
#define OFF_BHI (2 * 128 * SM_STRIDE)
#define OFF_BLO (3 * 128 * SM_STRIDE)
#define OFF_RED (4 * 128 * SM_STRIDE)
#define SM_TOTAL (OFF_RED + 2048)

template <int BN, int POOL>
__global__ void __launch_bounds__(256) k_mgemm(const float* __restrict__ A,
                                               const float* __restrict__ W,
                                               const float* __restrict__ bias,
                                               float* __restrict__ C,
                                               int Mm, int Nn, int Kk) {
    constexpr int WR = (BN == 128) ? 2 : 4;   // warp rows
    constexpr int WC = 8 / WR;                // warp cols
    constexpr int WM = 128 / WR;              // rows per warp
    constexpr int WN = BN / WC;               // 32 cols per warp
    constexpr int MA = WM / 16;               // m16 atoms per warp
    constexpr int NA = WN / 8;                // 4 n8 atoms per warp

    __shared__ __align__(16) char sm[SM_TOTAL];
    uint32_t sb = smem_u32(sm);

    int t = threadIdx.x, lane = t & 31, wid = t >> 5;
    int wrow = wid / WC, wcol = wid % WC;
    int row0 = blockIdx.y * 128, col0 = blockIdx.x * BN;

    // staging thread mapping: each thread owns one row, half the 16-k chunk
    int arow = t >> 1;
    int kh = (t & 1) * 8;
    uint32_t stA = sb + OFF_AHI + arow * SM_STRIDE + (t & 1) * 16;
    uint32_t stB = sb + OFF_BHI + arow * SM_STRIDE + (t & 1) * 16;
    const float* Abase = A + (size_t)(row0 + arow) * Kk + kh;
    const float* Wbase = (arow < BN) ? (W + (size_t)(col0 + arow) * Kk + kh) : nullptr;

    // ldmatrix addresses
    int lro = (lane & 7) + ((lane >> 3) & 1) * 8;
    int hob = (lane >> 4) * 16;
    uint32_t aAhi[MA], aAlo[MA], aBhi[2], aBlo[2];
#pragma unroll
    for (int ma = 0; ma < MA; ma++) {
        int rr = wrow * WM + ma * 16 + lro;
        aAhi[ma] = sb + OFF_AHI + rr * SM_STRIDE + hob;
        aAlo[ma] = sb + OFF_ALO + rr * SM_STRIDE + hob;
    }
#pragma unroll
    for (int p = 0; p < 2; p++) {
        int rr = wcol * WN + p * 16 + lro;
        aBhi[p] = sb + OFF_BHI + rr * SM_STRIDE + hob;
        aBlo[p] = sb + OFF_BLO + rr * SM_STRIDE + hob;
    }

    float acc[MA][NA][4];
#pragma unroll
    for (int ma = 0; ma < MA; ma++)
#pragma unroll
        for (int na = 0; na < NA; na++)
#pragma unroll
            for (int q = 0; q < 4; q++) acc[ma][na][q] = 0.f;

    int nch = (Kk + 15) / 16;

    // prologue: stage + store chunk 0
    {
        float av[8], bv[8];
#pragma unroll
        for (int q = 0; q < 8; q++) {
            int k = kh + q;
            av[q] = (k < Kk) ? Abase[q] : 0.f;
            bv[q] = (Wbase && k < Kk) ? Wbase[q] : 0.f;
        }
        uint4 hi, lo;
        cvt8(av, hi, lo);
        *(uint4*)(sm + (stA - sb)) = hi;
        *(uint4*)(sm + (stA - sb) + OFF_ALO) = lo;
        cvt8(bv, hi, lo);
        *(uint4*)(sm + (stB - sb)) = hi;
        *(uint4*)(sm + (stB - sb) + (OFF_BLO - OFF_BHI)) = lo;
    }
    __syncthreads();

    for (int ch = 0; ch < nch; ch++) {
        float av[8], bv[8];
        bool more = (ch + 1) < nch;
        if (more) {
            int kb = (ch + 1) * 16;
#pragma unroll
            for (int q = 0; q < 8; q++) {
                int k = kb + kh + q;
                av[q] = (k < Kk) ? Abase[kb + q] : 0.f;
                bv[q] = (Wbase && k < Kk) ? Wbase[kb + q] : 0.f;
            }
        }

        uint32_t ah[MA][4], al[MA][4], bh[2][4], bl[2][4];
#pragma unroll
        for (int ma = 0; ma < MA; ma++) {
            ldmx4(ah[ma], aAhi[ma]);
            ldmx4(al[ma], aAlo[ma]);
        }
#pragma unroll
        for (int p = 0; p < 2; p++) {
            ldmx4(bh[p], aBhi[p]);
            ldmx4(bl[p], aBlo[p]);
        }
#pragma unroll
        for (int ma = 0; ma < MA; ma++)
#pragma unroll
            for (int na = 0; na < NA; na++) {
                uint32_t bbh[2] = {bh[na >> 1][na & 1], bh[na >> 1][(na & 1) + 2]};
                uint32_t bbl[2] = {bl[na >> 1][na & 1], bl[na >> 1][(na & 1) + 2]};
                mma16816(acc[ma][na], ah[ma], bbh);
                mma16816(acc[ma][na], ah[ma], bbl);
                mma16816(acc[ma][na], al[ma], bbh);
            }
        __syncthreads();
        if (more) {
            uint4 hi, lo;
            cvt8(av, hi, lo);
            *(uint4*)(sm + (stA - sb)) = hi;
            *(uint4*)(sm + (stA - sb) + OFF_ALO) = lo;
            cvt8(bv, hi, lo);
            *(uint4*)(sm + (stB - sb)) = hi;
            *(uint4*)(sm + (stB - sb) + (OFF_BLO - OFF_BHI)) = lo;
            __syncthreads();
        }
    }

    int tg = lane >> 2, t4 = lane & 3;

    if (POOL == 0) {
#pragma unroll
        for (int ma = 0; ma < MA; ma++)
#pragma unroll
            for (int na = 0; na < NA; na++) {
                int cb = col0 + wcol * WN + na * 8 + t4 * 2;
                float b0 = bias[cb], b1 = bias[cb + 1];
#pragma unroll
                for (int h = 0; h < 2; h++) {
                    int r = row0 + wrow * WM + ma * 16 + tg + h * 8;
                    float v0 = fmaxf(acc[ma][na][h * 2 + 0] + b0, 0.f);
                    float v1 = fmaxf(acc[ma][na][h * 2 + 1] + b1, 0.f);
                    float* Cp = &C[(size_t)r * Nn + cb];
                    Cp[0] = v0; Cp[1] = v1;
                }
            }
    } else {
        const int NG = 128 / POOL;
        int* red = (int*)(sm + OFF_RED);
        for (int i = t; i < NG * BN; i += 256) red[i] = 0;
        __syncthreads();
#pragma unroll
        for (int ma = 0; ma < MA; ma++)
#pragma unroll
            for (int na = 0; na < NA; na++) {
                int cb = wcol * WN + na * 8 + t4 * 2;
                float b0 = bias[col0 + cb], b1 = bias[col0 + cb + 1];
#pragma unroll
                for (int h = 0; h < 2; h++) {
                    int rt = wrow * WM + ma * 16 + tg + h * 8;
                    int g = rt / POOL;
                    float v0 = fmaxf(acc[ma][na][h * 2 + 0] + b0, 0.f);
                    float v1 = fmaxf(acc[ma][na][h * 2 + 1] + b1, 0.f);
                    atomicMax(&red[g * BN + cb], __float_as_int(v0));
                    atomicMax(&red[g * BN + cb + 1], __float_as_int(v1));
                }
            }
        __syncthreads();
        for (int i = t; i < NG * BN; i += 256) {
            int g = i / BN, lc = i % BN;
            C[(size_t)(row0 / POOL + g) * Nn + col0 + lc] = __int_as_float(red[i]);
        }
    }
}

// ---------------- SIMT f32x2 GEMM (K=3 layer + tiny glob layers) ----------------
__global__ void __launch_bounds__(256, 2) k_gemm2(const float* __restrict__ A,
                                                  const float* __restrict__ W,
                                                  const float* __restrict__ bias,
                                                  float* __restrict__ C,
                                                  int Mm, int Nn, int Kk, int relu) {
    __shared__ float As2[2][16][256];
    __shared__ float Bs[2][16][128];
    int t = threadIdx.x;
    int tx = t & 15, ty = t >> 4;
    int row0 = blockIdx.y * 128, col0 = blockIdx.x * 128;
    int lrow = t >> 1;
    int lk = (t & 1) * 8;
    bool aok = (row0 + lrow) < Mm;
    bool bok = (col0 + lrow) < Nn;
    const float* Ap = A + (size_t)(row0 + lrow) * Kk;
    const float* Wp = W + (size_t)(col0 + lrow) * Kk;

    unsigned long long acc[8][4];
#pragma unroll
    for (int i = 0; i < 8; i++)
#pragma unroll
        for (int j = 0; j < 4; j++) acc[i][j] = 0ull;

    int nchunks = (Kk + 15) / 16;
    {
        float av[8], bv[8];
#pragma unroll
        for (int q = 0; q < 8; q++) {
            int k = lk + q;
            av[q] = (aok && k < Kk) ? Ap[k] : 0.f;
            bv[q] = (bok && k < Kk) ? Wp[k] : 0.f;
        }
#pragma unroll
        for (int q = 0; q < 8; q++) {
            *(float2*)&As2[0][lk + q][2 * lrow] = make_float2(av[q], av[q]);
            Bs[0][lk + q][lrow] = bv[q];
        }
    }
    __syncthreads();

    for (int c = 0; c < nchunks; c++) {
        int buf = c & 1;
        float av[8], bv[8];
        bool more = (c + 1) < nchunks;
        if (more) {
            int k0 = (c + 1) * 16;
#pragma unroll
            for (int q = 0; q < 8; q++) {
                int k = k0 + lk + q;
                av[q] = (aok && k < Kk) ? Ap[k] : 0.f;
                bv[q] = (bok && k < Kk) ? Wp[k] : 0.f;
            }
        }
#pragma unroll
        for (int kk = 0; kk < 16; kk++) {
            const float* arow = As2[buf][kk];
            const float* brow = Bs[buf][kk];
            ulonglong2 aA = *(const ulonglong2*)(arow + ty * 8);
            ulonglong2 aB = *(const ulonglong2*)(arow + ty * 8 + 4);
            ulonglong2 aC = *(const ulonglong2*)(arow + 128 + ty * 8);
            ulonglong2 aD = *(const ulonglong2*)(arow + 128 + ty * 8 + 4);
            ulonglong2 b01 = *(const ulonglong2*)(brow + tx * 4);
            ulonglong2 b23 = *(const ulonglong2*)(brow + 64 + tx * 4);
            unsigned long long ar[8] = {aA.x, aA.y, aB.x, aB.y, aC.x, aC.y, aD.x, aD.y};
            unsigned long long br[4] = {b01.x, b01.y, b23.x, b23.y};
#pragma unroll
            for (int i = 0; i < 8; i++)
#pragma unroll
                for (int j = 0; j < 4; j++)
                    asm("fma.rn.f32x2 %0, %1, %2, %0;" : "+l"(acc[i][j]) : "l"(ar[i]), "l"(br[j]));
        }
        if (more) {
            int nb = buf ^ 1;
#pragma unroll
            for (int q = 0; q < 8; q++) {
                *(float2*)&As2[nb][lk + q][2 * lrow] = make_float2(av[q], av[q]);
                Bs[nb][lk + q][lrow] = bv[q];
            }
        }
        __syncthreads();
    }

#pragma unroll
    for (int blk = 0; blk < 2; blk++) {
#pragma unroll
        for (int i = 0; i < 4; i++) {
            int r = row0 + blk * 64 + ty * 4 + i;
            if (r >= Mm) continue;
#pragma unroll
            for (int jp = 0; jp < 4; jp++) {
                float2 v;
                asm("mov.b64 {%0, %1}, %2;" : "=f"(v.x), "=f"(v.y) : "l"(acc[blk * 4 + i][jp]));
                int cc = col0 + (jp >> 1) * 64 + tx * 4 + (jp & 1) * 2;
                if (cc < Nn) {
                    float x = v.x + bias[cc];
                    if (relu) x = fmaxf(x, 0.f);
                    C[(size_t)r * Nn + cc] = x;
                }
                if (cc + 1 < Nn) {
                    float x = v.y + bias[cc + 1];
                    if (relu) x = fmaxf(x, 0.f);
                    C[(size_t)r * Nn + cc + 1] = x;
                }
            }
        }
    }
}

// ---------------- host ----------------
static void* sym_addr(const void* sym) {
    void* p = nullptr;
    cudaGetSymbolAddress(&p, sym);
    return p;
}

static inline void gemm_s(const float* A, const float* W, const float* b, float* C,
                          int M, int N, int K, int relu) {
    dim3 grid((N + 127) / 128, (M + 127) / 128);
    k_gemm2<<<grid, 256>>>(A, W, b, C, M, N, K, relu);
}

template <int BN, int POOL>
static inline void gemm_t(const float* A, const float* W, const float* b, float* C,
                          int M, int N, int K) {
    dim3 grid(N / BN, M / 128);
    k_mgemm<BN, POOL><<<grid, 256>>>(A, W, b, C, M, N, K);
}

extern "C" void kernel_launch(void* const* d_in, const int* in_sizes, int n_in,
                              void* d_out, int out_size) {
    const float* pts = (const float*)d_in[0];
    const float* sa1w0 = (const float*)d_in[1];  const float* sa1b0 = (const float*)d_in[2];
    const float* sa1w1 = (const float*)d_in[3];  const float* sa1b1 = (const float*)d_in[4];
    const float* sa1w2 = (const float*)d_in[5];  const float* sa1b2 = (const float*)d_in[6];
    const float* sa2w0 = (const float*)d_in[7];  const float* sa2b0 = (const float*)d_in[8];
    const float* sa2w1 = (const float*)d_in[9];  const float* sa2b1 = (const float*)d_in[10];
    const float* sa2w2 = (const float*)d_in[11]; const float* sa2b2 = (const float*)d_in[12];
    const float* locw0 = (const float*)d_in[13]; const float* locb0 = (const float*)d_in[14];
    const float* locw1 = (const float*)d_in[15]; const float* locb1 = (const float*)d_in[16];
    const float* locw2 = (const float*)d_in[17]; const float* locb2 = (const float*)d_in[18];
    const float* glow0 = (const float*)d_in[19]; const float* glob0 = (const float*)d_in[20];
    const float* glow1 = (const float*)d_in[21]; const float* glob1 = (const float*)d_in[22];
    const float* clsw  = (const float*)d_in[23]; const float* clsb  = (const float*)d_in[24];
    float* out = (float*)d_out;

    float* xyz     = (float*)sym_addr(g_xyz);
    float* nx1     = (float*)sym_addr(g_newxyz1);
    float* nx2     = (float*)sym_addr(g_newxyz2);
    int*   ball1   = (int*)  sym_addr(g_ball1);
    int*   ball2   = (int*)  sym_addr(g_ball2);
    float* grouped = (float*)sym_addr(g_grouped);
    float* bufA    = (float*)sym_addr(g_bufA);
    float* bufB    = (float*)sym_addr(g_bufB);
    float* feats1  = (float*)sym_addr(g_feats1);
    float* feats2  = (float*)sym_addr(g_feats2);
    float* pool    = (float*)sym_addr(g_pool);
    float* gg1     = (float*)sym_addr(g_g1);
    float* gg2     = (float*)sym_addr(g_g2);

    const float R2_1 = (float)(0.2 * 0.2);
    const float R2_2 = (float)(0.4 * 0.4);

    // 1. transpose
    k_transpose<<<(BATCH * 3 * NPTS1 + 255) / 256, 256>>>(pts);

    // 2. SA1
    k_fps<8, NPTS1, M1><<<BATCH, 1024>>>(xyz, nx1);
    k_ballquery<NPTS1, M1, KNN1><<<(BATCH * M1) / 8, 256>>>(xyz, nx1, R2_1, ball1);
    k_group1<<<(BATCH * M1 * KNN1 + 255) / 256, 256>>>();
    gemm_s(grouped, sa1w0, sa1b0, bufA, BATCH * M1 * KNN1, 64, 3, 1);   // K=3: SIMT
    gemm_t<64, 0>(bufA, sa1w1, sa1b1, bufB, BATCH * M1 * KNN1, 64, 64);
    gemm_t<128, KNN1>(bufB, sa1w2, sa1b2, feats1, BATCH * M1 * KNN1, 128, 64);

    // 3. SA2
    k_fps<1, NPTS2, M2><<<BATCH, 512>>>(nx1, nx2);
    k_ballquery<NPTS2, M2, KNN2><<<(BATCH * M2) / 8, 256>>>(nx1, nx2, R2_2, ball2);
    k_group2<<<(BATCH * M2 * KNN2 * 32 + 255) / 256, 256>>>();
    gemm_t<128, 0>(grouped, sa2w0, sa2b0, bufA, BATCH * M2 * KNN2, 128, 131);
    gemm_t<128, 0>(bufA, sa2w1, sa2b1, bufB, BATCH * M2 * KNN2, 128, 128);
    gemm_t<128, KNN2>(bufB, sa2w2, sa2b2, feats2, BATCH * M2 * KNN2, 256, 128);

    // 4. loc MLP + global max-pool
    gemm_t<128, 0>(feats2, locw0, locb0, bufA, BATCH * M2, 256, 256);
    gemm_t<128, 0>(bufA, locw1, locb1, bufB, BATCH * M2, 512, 256);
    gemm_t<128, 128>(bufB, locw2, locb2, pool, BATCH * M2, 1024, 512);

    // 5. global MLP (tiny; SIMT)
    gemm_s(pool, glow0, glob0, gg1, BATCH, 512, 1024, 1);
    gemm_s(gg1,  glow1, glob1, gg2, BATCH, 256, 512, 1);
    gemm_s(gg2,  clsw,  clsb,  out, BATCH, 40, 256, 0);
}